// round 1
// baseline (speedup 1.0000x reference)
#include <cuda_runtime.h>

#define BATCH 8
#define NSEQ  4096
#define DIM   384
#define HEADS 6
#define DHEAD 64
#define INNER 384
#define ROWS  (BATCH*NSEQ)   // 32768

// ---- scratch (device globals: no allocation allowed) ----
__device__ float g_q   [ (size_t)ROWS*INNER ];
__device__ float g_k   [ (size_t)ROWS*INNER ];
__device__ float g_v   [ (size_t)ROWS*INNER ];
__device__ float g_attn[ (size_t)ROWS*INNER ];
__device__ float g_kv  [ BATCH*HEADS*DHEAD*DHEAD ];
__device__ float g_ksum[ BATCH*HEADS*DHEAD ];

__device__ __forceinline__ float elu1(float x) {
    // elu(x)+1 == x+1 (x>0) else exp(x)
    return x > 0.f ? x + 1.f : __expf(x);
}

// ---------------------------------------------------------------------------
// Tiled SGEMM: C[M,N] = A[M,K] @ B[K,N]
// BM=BN=128, BK=16, 256 threads, each thread 8x8 outputs.
// EPI 0: C = acc + bias[c]
// EPI 1: C = elu1(acc)
// EPI 2: split at N/2: first half -> C (elu1), second half -> C2 (raw),
//        both stored with row stride N/2.
// Requires M%128==0, N%128==0, K%16==0 (true for all call sites).
// ---------------------------------------------------------------------------
template<int EPI>
__global__ __launch_bounds__(256)
void sgemm_kernel(const float* __restrict__ A, const float* __restrict__ Bm,
                  float* __restrict__ C, float* __restrict__ C2,
                  const float* __restrict__ bias, int M, int N, int K)
{
    const int BM = 128, BN = 128, BK = 16;
    __shared__ float As[BK][BM];   // transposed A tile
    __shared__ float Bs[BK][BN];

    const int tid = threadIdx.x;
    const int tx = tid % 16;          // col group (8 cols each)
    const int ty = tid / 16;          // row group (8 rows each)
    const int row0 = blockIdx.y * BM;
    const int col0 = blockIdx.x * BN;

    float acc[8][8];
    #pragma unroll
    for (int i = 0; i < 8; i++)
        #pragma unroll
        for (int j = 0; j < 8; j++) acc[i][j] = 0.f;

    for (int k0 = 0; k0 < K; k0 += BK) {
        // load A tile (BM x BK) -> As[c][r]
        #pragma unroll
        for (int i = tid; i < BM*BK; i += 256) {
            int r = i >> 4, c = i & 15;
            As[c][r] = A[(size_t)(row0 + r) * K + k0 + c];
        }
        // load B tile (BK x BN)
        #pragma unroll
        for (int i = tid; i < BK*BN; i += 256) {
            int r = i >> 7, c = i & 127;
            Bs[r][c] = Bm[(size_t)(k0 + r) * N + col0 + c];
        }
        __syncthreads();

        #pragma unroll
        for (int kk = 0; kk < BK; kk++) {
            float4 a0 = *reinterpret_cast<const float4*>(&As[kk][ty*8]);
            float4 a1 = *reinterpret_cast<const float4*>(&As[kk][ty*8 + 4]);
            float4 b0 = *reinterpret_cast<const float4*>(&Bs[kk][tx*8]);
            float4 b1 = *reinterpret_cast<const float4*>(&Bs[kk][tx*8 + 4]);
            float ra[8] = {a0.x,a0.y,a0.z,a0.w,a1.x,a1.y,a1.z,a1.w};
            float rb[8] = {b0.x,b0.y,b0.z,b0.w,b1.x,b1.y,b1.z,b1.w};
            #pragma unroll
            for (int i = 0; i < 8; i++)
                #pragma unroll
                for (int j = 0; j < 8; j++)
                    acc[i][j] += ra[i] * rb[j];
        }
        __syncthreads();
    }

    // epilogue
    #pragma unroll
    for (int i = 0; i < 8; i++) {
        const int r = row0 + ty*8 + i;
        #pragma unroll
        for (int j = 0; j < 8; j++) {
            const int c = col0 + tx*8 + j;
            float vv = acc[i][j];
            if (EPI == 0) {
                C[(size_t)r * N + c] = vv + bias[c];
            } else if (EPI == 1) {
                C[(size_t)r * N + c] = elu1(vv);
            } else {
                const int half = N >> 1;
                if (c < half) C [(size_t)r * half + c]          = elu1(vv);
                else          C2[(size_t)r * half + (c - half)] = vv;
            }
        }
    }
}

// ---------------------------------------------------------------------------
// Zero kv / ksum accumulators
// ---------------------------------------------------------------------------
__global__ void zero_kernel()
{
    int i = blockIdx.x * 256 + threadIdx.x;
    if (i < BATCH*HEADS*DHEAD*DHEAD) g_kv[i] = 0.f;
    if (i < BATCH*HEADS*DHEAD)       g_ksum[i] = 0.f;
}

// ---------------------------------------------------------------------------
// kv[bh][d][m] = sum_n k[b,n,h,d] * v[b,n,h,m];  ksum[bh][d] = sum_n k
// grid: (BATCH*HEADS, NSEQ/CHUNK), block 256.
// Each thread owns one d (tid/4) and 16 m-columns ((tid&3)*16).
// ---------------------------------------------------------------------------
#define CHUNK 256
__global__ __launch_bounds__(256)
void kv_reduce_kernel()
{
    const int bh = blockIdx.x;
    const int b = bh / HEADS, h = bh % HEADS;
    const int n0 = blockIdx.y * CHUNK;
    __shared__ float Ks[16][64];
    __shared__ float Vs[16][64];

    const int tid = threadIdx.x;
    const int d  = tid >> 2;
    const int mb = (tid & 3) * 16;

    float acc[16];
    #pragma unroll
    for (int j = 0; j < 16; j++) acc[j] = 0.f;
    float sk = 0.f;

    const float* kptr = g_k + ((size_t)b * NSEQ) * INNER + h * DHEAD;
    const float* vptr = g_v + ((size_t)b * NSEQ) * INNER + h * DHEAD;

    for (int nn = n0; nn < n0 + CHUNK; nn += 16) {
        #pragma unroll
        for (int i = tid; i < 16*64; i += 256) {
            int r = i >> 6, c = i & 63;
            Ks[r][c] = kptr[(size_t)(nn + r) * INNER + c];
            Vs[r][c] = vptr[(size_t)(nn + r) * INNER + c];
        }
        __syncthreads();
        #pragma unroll
        for (int kk = 0; kk < 16; kk++) {
            float kd = Ks[kk][d];
            sk += kd;
            float4 v0 = *reinterpret_cast<const float4*>(&Vs[kk][mb]);
            float4 v1 = *reinterpret_cast<const float4*>(&Vs[kk][mb + 4]);
            float4 v2 = *reinterpret_cast<const float4*>(&Vs[kk][mb + 8]);
            float4 v3 = *reinterpret_cast<const float4*>(&Vs[kk][mb + 12]);
            float rv[16] = {v0.x,v0.y,v0.z,v0.w, v1.x,v1.y,v1.z,v1.w,
                            v2.x,v2.y,v2.z,v2.w, v3.x,v3.y,v3.z,v3.w};
            #pragma unroll
            for (int j = 0; j < 16; j++) acc[j] += kd * rv[j];
        }
        __syncthreads();
    }

    float* kvp = g_kv + ((size_t)bh * DHEAD + d) * DHEAD + mb;
    #pragma unroll
    for (int j = 0; j < 16; j++) atomicAdd(&kvp[j], acc[j]);
    if ((tid & 3) == 0) atomicAdd(&g_ksum[bh * DHEAD + d], sk);
}

// ---------------------------------------------------------------------------
// attn[b,n,h,m] = (sum_d q[b,n,h,d]*kv[bh][d][m]) / (q[b,n,h,:].ksum[bh] + 1e-6)
// grid: (BATCH*HEADS, NSEQ/64), block 256. kv tile resident in smem.
// ---------------------------------------------------------------------------
__global__ __launch_bounds__(256)
void attn_out_kernel()
{
    const int bh = blockIdx.x;
    const int b = bh / HEADS, h = bh % HEADS;
    const int n0 = blockIdx.y * 64;

    __shared__ float kvs[64][64];
    __shared__ float qs[64][65];   // padded: avoid bank conflicts on column reads
    __shared__ float ksums[64];
    __shared__ float zr[64];

    const int tid = threadIdx.x;

    #pragma unroll
    for (int i = tid; i < 4096; i += 256)
        kvs[i >> 6][i & 63] = g_kv[(size_t)bh * 4096 + i];
    if (tid < 64) ksums[tid] = g_ksum[bh * 64 + tid];

    const float* qptr = g_q + ((size_t)b * NSEQ + n0) * INNER + h * DHEAD;
    #pragma unroll
    for (int i = tid; i < 4096; i += 256) {
        int r = i >> 6, c = i & 63;
        qs[r][c] = qptr[(size_t)r * INNER + c];
    }
    __syncthreads();

    if (tid < 64) {
        float s = 0.f;
        #pragma unroll
        for (int dd = 0; dd < 64; dd++) s += qs[tid][dd] * ksums[dd];
        zr[tid] = 1.f / (s + 1e-6f);
    }
    __syncthreads();

    const int r  = tid >> 2;
    const int mb = (tid & 3) * 16;
    float acc[16];
    #pragma unroll
    for (int j = 0; j < 16; j++) acc[j] = 0.f;

    #pragma unroll
    for (int dd = 0; dd < 64; dd++) {
        float qv = qs[r][dd];
        float4 v0 = *reinterpret_cast<const float4*>(&kvs[dd][mb]);
        float4 v1 = *reinterpret_cast<const float4*>(&kvs[dd][mb + 4]);
        float4 v2 = *reinterpret_cast<const float4*>(&kvs[dd][mb + 8]);
        float4 v3 = *reinterpret_cast<const float4*>(&kvs[dd][mb + 12]);
        float rv[16] = {v0.x,v0.y,v0.z,v0.w, v1.x,v1.y,v1.z,v1.w,
                        v2.x,v2.y,v2.z,v2.w, v3.x,v3.y,v3.z,v3.w};
        #pragma unroll
        for (int j = 0; j < 16; j++) acc[j] += qv * rv[j];
    }

    const float z = zr[r];
    float* optr = g_attn + ((size_t)b * NSEQ + n0 + r) * INNER + h * DHEAD + mb;
    #pragma unroll
    for (int j = 0; j < 16; j++) optr[j] = acc[j] * z;
}

// ---------------------------------------------------------------------------
extern "C" void kernel_launch(void* const* d_in, const int* in_sizes, int n_in,
                              void* d_out, int out_size)
{
    const float* x_q  = (const float*)d_in[0];
    const float* x_kv = (const float*)d_in[1];
    const float* Wq   = (const float*)d_in[2];
    const float* Wkv  = (const float*)d_in[3];
    const float* Wout = (const float*)d_in[4];
    const float* bout = (const float*)d_in[5];
    float* out = (float*)d_out;

    float *qp, *kp, *vp, *ap;
    cudaGetSymbolAddress((void**)&qp, g_q);
    cudaGetSymbolAddress((void**)&kp, g_k);
    cudaGetSymbolAddress((void**)&vp, g_v);
    cudaGetSymbolAddress((void**)&ap, g_attn);

    dim3 blk(256);

    // 1) q = elu1(x_q @ Wq)
    sgemm_kernel<1><<<dim3(INNER/128, ROWS/128), blk>>>(
        x_q, Wq, qp, nullptr, nullptr, ROWS, INNER, DIM);

    // 2) kv_proj = x_kv @ Wkv -> k (elu1) / v (raw)
    sgemm_kernel<2><<<dim3(2*INNER/128, ROWS/128), blk>>>(
        x_kv, Wkv, kp, vp, nullptr, ROWS, 2*INNER, DIM);

    // 3) kv = k^T v per (b,h); ksum = sum_n k
    zero_kernel<<<(BATCH*HEADS*DHEAD*DHEAD + 255)/256, blk>>>();
    kv_reduce_kernel<<<dim3(BATCH*HEADS, NSEQ/CHUNK), blk>>>();

    // 4) attn = (q @ kv) * z
    attn_out_kernel<<<dim3(BATCH*HEADS, NSEQ/64), blk>>>();

    // 5) out = attn @ Wout + bout
    sgemm_kernel<0><<<dim3(INNER/128, ROWS/128), blk>>>(
        ap, Wout, out, nullptr, bout, ROWS, INNER, DIM);
}

// round 3
// speedup vs baseline: 3.2199x; 3.2199x over previous
#include <cuda_runtime.h>
#include <cstdint>

#define BATCH 8
#define NSEQ  4096
#define DIM   384
#define HEADS 6
#define DHEAD 64
#define INNER 384
#define ROWS  (BATCH*NSEQ)   // 32768

// ---- scratch (device globals: no allocation allowed) ----
__device__ float g_q   [ (size_t)ROWS*INNER ];
__device__ float g_k   [ (size_t)ROWS*INNER ];
__device__ float g_v   [ (size_t)ROWS*INNER ];
__device__ float g_attn[ (size_t)ROWS*INNER ];
__device__ float g_kv  [ BATCH*HEADS*DHEAD*DHEAD ];
__device__ float g_ksum[ BATCH*HEADS*DHEAD ];

__device__ __forceinline__ float elu1(float x) {
    return x > 0.f ? x + 1.f : __expf(x);
}

__device__ __forceinline__ uint32_t f2tf32(float x) {
    uint32_t u;
    asm("cvt.rna.tf32.f32 %0, %1;" : "=r"(u) : "f"(x));
    return u;
}

__device__ __forceinline__ void mma_tf32(float c[4], uint32_t a0, uint32_t a1,
                                         uint32_t a2, uint32_t a3,
                                         uint32_t b0, uint32_t b1) {
    asm volatile(
        "mma.sync.aligned.m16n8k8.row.col.f32.tf32.tf32.f32 "
        "{%0,%1,%2,%3}, {%4,%5,%6,%7}, {%8,%9}, {%0,%1,%2,%3};"
        : "+f"(c[0]), "+f"(c[1]), "+f"(c[2]), "+f"(c[3])
        : "r"(a0), "r"(a1), "r"(a2), "r"(a3), "r"(b0), "r"(b1));
}

// ============================================================================
// tf32 mma.sync GEMM: C[M,N] = A[M,K] @ B[K,N], fp32 in/out.
// CTA tile 128x128, BK=32, 256 threads (8 warps; warp grid 2(M) x 4(N),
// warp tile 64x32). M%128==0, N%128==0, K%32==0 at all call sites.
// EPI 0: C = acc + bias[c]
// EPI 1: C = elu1(acc)
// EPI 2: split at N/2: col<half -> C (elu1) else C2 (raw), row stride half.
// ============================================================================
#define APITCH 36    // floats per As row  (conflict-free frag loads)
#define BPITCH 132   // floats per Bs row

template<int EPI>
__global__ __launch_bounds__(256)
void mma_gemm(const float* __restrict__ A, const float* __restrict__ B,
              float* __restrict__ C, float* __restrict__ C2,
              const float* __restrict__ bias, int N, int K)
{
    __shared__ uint32_t As[128 * APITCH];   // [m][k], tf32 bits
    __shared__ uint32_t Bs[32  * BPITCH];   // [k][n], tf32 bits

    const int tid  = threadIdx.x;
    const int wid  = tid >> 5;
    const int lane = tid & 31;
    const int wm   = (wid & 1) * 64;    // warp m offset within CTA
    const int wn   = (wid >> 1) * 32;   // warp n offset within CTA
    const int row0 = blockIdx.y * 128;
    const int col0 = blockIdx.x * 128;

    const int lr = lane >> 2;   // 0..7
    const int lc = lane & 3;    // 0..3

    float acc[4][4][4];
    #pragma unroll
    for (int i = 0; i < 4; i++)
        #pragma unroll
        for (int j = 0; j < 4; j++)
            #pragma unroll
            for (int r = 0; r < 4; r++) acc[i][j][r] = 0.f;

    for (int k0 = 0; k0 < K; k0 += 32) {
        // ---- load A tile: 128 x 32 (1024 float4 slots) ----
        #pragma unroll
        for (int j = 0; j < 4; j++) {
            int idx = tid + 256 * j;
            int r = idx >> 3, c4 = (idx & 7) * 4;
            float4 v = *reinterpret_cast<const float4*>(
                &A[(size_t)(row0 + r) * K + k0 + c4]);
            uint32_t* dst = &As[r * APITCH + c4];
            dst[0] = f2tf32(v.x); dst[1] = f2tf32(v.y);
            dst[2] = f2tf32(v.z); dst[3] = f2tf32(v.w);
        }
        // ---- load B tile: 32 x 128 (1024 float4 slots) ----
        #pragma unroll
        for (int j = 0; j < 4; j++) {
            int idx = tid + 256 * j;
            int r = idx >> 5, c4 = (idx & 31) * 4;
            float4 v = *reinterpret_cast<const float4*>(
                &B[(size_t)(k0 + r) * N + col0 + c4]);
            uint32_t* dst = &Bs[r * BPITCH + c4];
            dst[0] = f2tf32(v.x); dst[1] = f2tf32(v.y);
            dst[2] = f2tf32(v.z); dst[3] = f2tf32(v.w);
        }
        __syncthreads();

        #pragma unroll
        for (int s = 0; s < 4; s++) {
            const int kk = s * 8;
            // A fragments: 4 m-tiles
            uint32_t af[4][4];
            #pragma unroll
            for (int mt = 0; mt < 4; mt++) {
                const uint32_t* ap = &As[(wm + mt * 16 + lr) * APITCH + kk + lc];
                af[mt][0] = ap[0];
                af[mt][1] = ap[8 * APITCH];
                af[mt][2] = ap[4];
                af[mt][3] = ap[8 * APITCH + 4];
            }
            // B fragments: 4 n-tiles
            uint32_t bf[4][2];
            #pragma unroll
            for (int nt = 0; nt < 4; nt++) {
                const uint32_t* bp = &Bs[(kk + lc) * BPITCH + wn + nt * 8 + lr];
                bf[nt][0] = bp[0];
                bf[nt][1] = bp[4 * BPITCH];
            }
            #pragma unroll
            for (int mt = 0; mt < 4; mt++)
                #pragma unroll
                for (int nt = 0; nt < 4; nt++)
                    mma_tf32(acc[mt][nt], af[mt][0], af[mt][1], af[mt][2],
                             af[mt][3], bf[nt][0], bf[nt][1]);
        }
        __syncthreads();
    }

    // ---- epilogue ----
    const int half = N >> 1;
    #pragma unroll
    for (int mt = 0; mt < 4; mt++) {
        #pragma unroll
        for (int nt = 0; nt < 4; nt++) {
            const int col = col0 + wn + nt * 8 + lc * 2;
            #pragma unroll
            for (int hh = 0; hh < 2; hh++) {
                const int row = row0 + wm + mt * 16 + lr + hh * 8;
                float v0 = acc[mt][nt][hh * 2 + 0];
                float v1 = acc[mt][nt][hh * 2 + 1];
                float2 o;
                if (EPI == 0) {
                    o.x = v0 + bias[col]; o.y = v1 + bias[col + 1];
                    *reinterpret_cast<float2*>(&C[(size_t)row * N + col]) = o;
                } else if (EPI == 1) {
                    o.x = elu1(v0); o.y = elu1(v1);
                    *reinterpret_cast<float2*>(&C[(size_t)row * N + col]) = o;
                } else {
                    if (col < half) {
                        o.x = elu1(v0); o.y = elu1(v1);
                        *reinterpret_cast<float2*>(&C[(size_t)row * half + col]) = o;
                    } else {
                        o.x = v0; o.y = v1;
                        *reinterpret_cast<float2*>(&C2[(size_t)row * half + (col - half)]) = o;
                    }
                }
            }
        }
    }
}

// ---------------------------------------------------------------------------
// Zero kv / ksum accumulators
// ---------------------------------------------------------------------------
__global__ void zero_kernel()
{
    int i = blockIdx.x * 256 + threadIdx.x;
    if (i < BATCH*HEADS*DHEAD*DHEAD) g_kv[i] = 0.f;
    if (i < BATCH*HEADS*DHEAD)       g_ksum[i] = 0.f;
}

// ---------------------------------------------------------------------------
// kv[bh][d][m] = sum_n k[b,n,h,d]*v[b,n,h,m];  ksum[bh][d] = sum_n k
// grid (48, NSEQ/CHUNK), 256 threads, 4x4 register tiles.
// ---------------------------------------------------------------------------
#define CHUNK 512
__global__ __launch_bounds__(256)
void kv_reduce_kernel()
{
    const int bh = blockIdx.x;
    const int b = bh / HEADS, h = bh % HEADS;
    const int n0 = blockIdx.y * CHUNK;
    __shared__ float Ks[32][64];
    __shared__ float Vs[32][64];

    const int tid = threadIdx.x;
    const int m0 = (tid & 15) * 4;
    const int d0 = (tid >> 4) * 4;

    float acc[4][4] = {};
    float sk[4] = {0.f, 0.f, 0.f, 0.f};

    const float* kptr = g_k + ((size_t)b * NSEQ) * INNER + h * DHEAD;
    const float* vptr = g_v + ((size_t)b * NSEQ) * INNER + h * DHEAD;

    for (int nn = n0; nn < n0 + CHUNK; nn += 32) {
        #pragma unroll
        for (int i = tid; i < 32 * 64; i += 256) {
            int r = i >> 6, c = i & 63;
            Ks[r][c] = kptr[(size_t)(nn + r) * INNER + c];
            Vs[r][c] = vptr[(size_t)(nn + r) * INNER + c];
        }
        __syncthreads();
        #pragma unroll
        for (int kk = 0; kk < 32; kk++) {
            float4 k4 = *reinterpret_cast<const float4*>(&Ks[kk][d0]);
            float4 v4 = *reinterpret_cast<const float4*>(&Vs[kk][m0]);
            float ka[4] = {k4.x, k4.y, k4.z, k4.w};
            float va[4] = {v4.x, v4.y, v4.z, v4.w};
            #pragma unroll
            for (int i = 0; i < 4; i++)
                #pragma unroll
                for (int j = 0; j < 4; j++)
                    acc[i][j] += ka[i] * va[j];
            if (m0 == 0) {
                sk[0] += ka[0]; sk[1] += ka[1]; sk[2] += ka[2]; sk[3] += ka[3];
            }
        }
        __syncthreads();
    }

    #pragma unroll
    for (int i = 0; i < 4; i++)
        #pragma unroll
        for (int j = 0; j < 4; j++)
            atomicAdd(&g_kv[((size_t)bh * DHEAD + d0 + i) * DHEAD + m0 + j], acc[i][j]);
    if (m0 == 0) {
        #pragma unroll
        for (int i = 0; i < 4; i++)
            atomicAdd(&g_ksum[bh * DHEAD + d0 + i], sk[i]);
    }
}

// ---------------------------------------------------------------------------
// attn[b,n,h,m] = (sum_d q*kv) * 1/(q . ksum + 1e-6)
// ---------------------------------------------------------------------------
__global__ __launch_bounds__(256)
void attn_out_kernel()
{
    const int bh = blockIdx.x;
    const int b = bh / HEADS, h = bh % HEADS;
    const int n0 = blockIdx.y * 64;

    __shared__ float kvs[64][64];
    __shared__ float qs[64][65];
    __shared__ float ksums[64];
    __shared__ float zr[64];

    const int tid = threadIdx.x;

    #pragma unroll
    for (int i = tid; i < 4096; i += 256)
        kvs[i >> 6][i & 63] = g_kv[(size_t)bh * 4096 + i];
    if (tid < 64) ksums[tid] = g_ksum[bh * 64 + tid];

    const float* qptr = g_q + ((size_t)b * NSEQ + n0) * INNER + h * DHEAD;
    #pragma unroll
    for (int i = tid; i < 4096; i += 256) {
        int r = i >> 6, c = i & 63;
        qs[r][c] = qptr[(size_t)r * INNER + c];
    }
    __syncthreads();

    if (tid < 64) {
        float s = 0.f;
        #pragma unroll
        for (int dd = 0; dd < 64; dd++) s += qs[tid][dd] * ksums[dd];
        zr[tid] = 1.f / (s + 1e-6f);
    }
    __syncthreads();

    const int r  = tid >> 2;
    const int mb = (tid & 3) * 16;
    float acc[16];
    #pragma unroll
    for (int j = 0; j < 16; j++) acc[j] = 0.f;

    #pragma unroll
    for (int dd = 0; dd < 64; dd++) {
        float qv = qs[r][dd];
        float4 v0 = *reinterpret_cast<const float4*>(&kvs[dd][mb]);
        float4 v1 = *reinterpret_cast<const float4*>(&kvs[dd][mb + 4]);
        float4 v2 = *reinterpret_cast<const float4*>(&kvs[dd][mb + 8]);
        float4 v3 = *reinterpret_cast<const float4*>(&kvs[dd][mb + 12]);
        float rv[16] = {v0.x,v0.y,v0.z,v0.w, v1.x,v1.y,v1.z,v1.w,
                        v2.x,v2.y,v2.z,v2.w, v3.x,v3.y,v3.z,v3.w};
        #pragma unroll
        for (int j = 0; j < 16; j++) acc[j] += qv * rv[j];
    }

    const float z = zr[r];
    float* optr = g_attn + ((size_t)b * NSEQ + n0 + r) * INNER + h * DHEAD + mb;
    #pragma unroll
    for (int j = 0; j < 16; j++) optr[j] = acc[j] * z;
}

// ---------------------------------------------------------------------------
extern "C" void kernel_launch(void* const* d_in, const int* in_sizes, int n_in,
                              void* d_out, int out_size)
{
    const float* x_q  = (const float*)d_in[0];
    const float* x_kv = (const float*)d_in[1];
    const float* Wq   = (const float*)d_in[2];
    const float* Wkv  = (const float*)d_in[3];
    const float* Wout = (const float*)d_in[4];
    const float* bout = (const float*)d_in[5];
    float* out = (float*)d_out;

    float *qp, *kp, *vp, *ap;
    cudaGetSymbolAddress((void**)&qp, g_q);
    cudaGetSymbolAddress((void**)&kp, g_k);
    cudaGetSymbolAddress((void**)&vp, g_v);
    cudaGetSymbolAddress((void**)&ap, g_attn);

    dim3 blk(256);

    // 1) q = elu1(x_q @ Wq)
    mma_gemm<1><<<dim3(INNER/128, ROWS/128), blk>>>(
        x_q, Wq, qp, nullptr, nullptr, INNER, DIM);

    // 2) kv_proj = x_kv @ Wkv -> k (elu1) / v (raw)
    mma_gemm<2><<<dim3(2*INNER/128, ROWS/128), blk>>>(
        x_kv, Wkv, kp, vp, nullptr, 2*INNER, DIM);

    // 3) kv = k^T v per (b,h); ksum = sum_n k
    zero_kernel<<<(BATCH*HEADS*DHEAD*DHEAD + 255)/256, blk>>>();
    kv_reduce_kernel<<<dim3(BATCH*HEADS, NSEQ/CHUNK), blk>>>();

    // 4) attn = (q @ kv) * z
    attn_out_kernel<<<dim3(BATCH*HEADS, NSEQ/64), blk>>>();

    // 5) out = attn @ Wout + bout
    mma_gemm<0><<<dim3(INNER/128, ROWS/128), blk>>>(
        ap, Wout, out, nullptr, bout, INNER, DIM);
}